// round 3
// baseline (speedup 1.0000x reference)
#include <cuda_runtime.h>
#include <cuda_bf16.h>
#include <cstdint>
#include <cstddef>

#define Tn 512
#define Bn 64
#define In 1024
#define Hn 1024
#define MAll (Tn*Bn)          // 32768
#define Ksp 3072              // 3-term split K: [hi | lo | hi] (A)  /  [hi | hi | lo] (B)
#define N3 3072               // 3 gates * H
#define PLANE ((size_t)MAll*(size_t)Hn)

// ------------------------- scratch (static device allocations) -------------------------
__device__ __align__(256) __nv_bfloat16 g_x2[(size_t)MAll*Ksp];     // x split      (192 MB)
__device__ __align__(256) __nv_bfloat16 g_Wi2[(size_t)N3*Ksp];      // Wzi|Wri|Wci  ( 18 MB)
__device__ __align__(256) __nv_bfloat16 g_Wzr[(size_t)2048*Ksp];    // Wzh|Wrh      ( 12 MB)
__device__ __align__(256) __nv_bfloat16 g_Wc2[(size_t)1024*Ksp];    // Wch          (  6 MB)
__device__ __align__(256) float g_biasi[N3];                        // b?i + b?h
__device__ __align__(256) float g_xproj[(size_t)3*MAll*Hn];         // x proj + bias (402 MB)
__device__ __align__(256) float g_h[Bn*Hn];
__device__ __align__(256) __nv_bfloat16 g_h2[(size_t)Bn*Ksp];
__device__ __align__(256) float g_z[Bn*Hn];
__device__ __align__(256) __nv_bfloat16 g_rh2[(size_t)Bn*Ksp];
__device__ unsigned g_cnt;     // zero-initialized
__device__ unsigned g_epoch;   // monotonic across graph replays

// ------------------------- helpers -------------------------
__device__ __forceinline__ float sigm(float x){ return 1.0f/(1.0f + __expf(-x)); }

__device__ __forceinline__ void bsplit(float v, __nv_bfloat16 &hi, __nv_bfloat16 &lo){
  hi = __float2bfloat16(v);
  lo = __float2bfloat16(v - __bfloat162float(hi));
}

__device__ __forceinline__ void ldsm_x4(unsigned addr, unsigned &r0, unsigned &r1,
                                        unsigned &r2, unsigned &r3){
  asm volatile("ldmatrix.sync.aligned.m8n8.x4.shared.b16 {%0,%1,%2,%3}, [%4];\n"
    : "=r"(r0),"=r"(r1),"=r"(r2),"=r"(r3) : "r"(addr));
}
__device__ __forceinline__ void ldsm_x2(unsigned addr, unsigned &r0, unsigned &r1){
  asm volatile("ldmatrix.sync.aligned.m8n8.x2.shared.b16 {%0,%1}, [%2];\n"
    : "=r"(r0),"=r"(r1) : "r"(addr));
}
__device__ __forceinline__ void mma16816(float &c0,float &c1,float &c2,float &c3,
                                         unsigned a0,unsigned a1,unsigned a2,unsigned a3,
                                         unsigned b0,unsigned b1){
  asm volatile("mma.sync.aligned.m16n8k16.row.col.f32.bf16.bf16.f32 "
               "{%0,%1,%2,%3},{%4,%5,%6,%7},{%8,%9},{%0,%1,%2,%3};\n"
    : "+f"(c0),"+f"(c1),"+f"(c2),"+f"(c3)
    : "r"(a0),"r"(a1),"r"(a2),"r"(a3),"r"(b0),"r"(b1));
}
#define CP16(smem_u32, gptr) \
  asm volatile("cp.async.cg.shared.global [%0], [%1], 16;\n" :: "r"(smem_u32), "l"(gptr))
#define CP_COMMIT() asm volatile("cp.async.commit_group;\n")
#define CP_WAIT1()  asm volatile("cp.async.wait_group 1;\n")
#define CP_WAIT0()  asm volatile("cp.async.wait_group 0;\n")

// Grid barrier: epoch-monotonic (graph-replay safe), base epoch read per launch.
__device__ __forceinline__ void gridbar(unsigned target){
  __threadfence();
  __syncthreads();
  if (threadIdx.x == 0){
    unsigned old = atomicAdd(&g_cnt, 1);
    if (old == gridDim.x - 1){
      atomicExch(&g_cnt, 0);
      __threadfence();
      atomicAdd(&g_epoch, 1);
    } else {
      while (*(volatile unsigned*)&g_epoch < target) { __nanosleep(64); }
    }
  }
  __syncthreads();
}

// ------------------------- prep kernels -------------------------
__global__ void k_split_x(const float* __restrict__ x){
  size_t stride = (size_t)gridDim.x * blockDim.x;
  for (size_t i = (size_t)blockIdx.x*blockDim.x + threadIdx.x; i < (size_t)MAll*In; i += stride){
    size_t row = i >> 10; int col = (int)(i & 1023);
    __nv_bfloat16 hi, lo; bsplit(x[i], hi, lo);
    __nv_bfloat16* p = g_x2 + row*Ksp;
    p[col]        = hi;   // A-side: [hi | lo | hi]
    p[In + col]   = lo;
    p[2*In + col] = hi;
  }
}

// B-side split layout: [hi | hi | lo]
__device__ __forceinline__ void wsplit(float v, __nv_bfloat16* base, int c){
  __nv_bfloat16 hi, lo; bsplit(v, hi, lo);
  base[c]        = hi;
  base[In + c]   = hi;
  base[2*In + c] = lo;
}

__global__ void k_prep_w(const float* __restrict__ Wzi, const float* __restrict__ bzi,
                         const float* __restrict__ Wzh, const float* __restrict__ bzh,
                         const float* __restrict__ Wri, const float* __restrict__ bri,
                         const float* __restrict__ Wrh, const float* __restrict__ brh,
                         const float* __restrict__ Wci, const float* __restrict__ bci,
                         const float* __restrict__ Wch, const float* __restrict__ bch){
  int stride = gridDim.x * blockDim.x;
  for (int i = blockIdx.x*blockDim.x + threadIdx.x; i < Hn*In; i += stride){
    int r = i >> 10, c = i & 1023;
    wsplit(Wzi[i], g_Wi2 + (size_t)r*Ksp,        c);
    wsplit(Wri[i], g_Wi2 + (size_t)(Hn+r)*Ksp,   c);
    wsplit(Wci[i], g_Wi2 + (size_t)(2*Hn+r)*Ksp, c);
    wsplit(Wzh[i], g_Wzr + (size_t)r*Ksp,        c);
    wsplit(Wrh[i], g_Wzr + (size_t)(Hn+r)*Ksp,   c);
    wsplit(Wch[i], g_Wc2 + (size_t)r*Ksp,        c);
  }
  for (int n = blockIdx.x*blockDim.x + threadIdx.x; n < N3; n += stride){
    float b = (n < Hn)   ? (bzi[n] + bzh[n])
            : (n < 2*Hn) ? (bri[n-Hn] + brh[n-Hn])
                         : (bci[n-2*Hn] + bch[n-2*Hn]);
    g_biasi[n] = b;
  }
}

__global__ void k_init_h(const float* __restrict__ hidden){
  int stride = gridDim.x * blockDim.x;
  for (int i = blockIdx.x*blockDim.x + threadIdx.x; i < Bn*Hn; i += stride){
    int b = i >> 10, c = i & 1023;
    float v = hidden[i];
    g_h[i] = v;
    __nv_bfloat16 hi, lo; bsplit(v, hi, lo);
    __nv_bfloat16* p = g_h2 + (size_t)b*Ksp;
    p[c]        = hi;
    p[In + c]   = lo;
    p[2*In + c] = hi;
  }
}

// ------------------------- input projection GEMM -------------------------
// C[m, n] = sum_k x2[m,k] * Wi2[n,k] + bias[n]  ->  g_xproj[gate][m][n%1024]
// M=32768, N=3072, K=3072. BM=128, BN=128, BK=32, 256 threads (8 warps 4x2).
__global__ void __launch_bounds__(256,1) k_gemm_x(){
  __shared__ __align__(128) __nv_bfloat16 As[2][128*32];
  __shared__ __align__(128) __nv_bfloat16 Bs[2][128*32];
  const int tid = threadIdx.x, lane = tid & 31, wid = tid >> 5;
  const int wm = wid & 3, wn = wid >> 2;                 // warp tile 32m x 64n
  const int m0 = blockIdx.y * 128, n0 = blockIdx.x * 128;
  const unsigned sA = (unsigned)__cvta_generic_to_shared(&As[0][0]);
  const unsigned sB = (unsigned)__cvta_generic_to_shared(&Bs[0][0]);
  const __nv_bfloat16* Ag = g_x2 + (size_t)m0 * Ksp;
  const __nv_bfloat16* Bg = g_Wi2 + (size_t)n0 * Ksp;

  float acc[2][8][4];
  #pragma unroll
  for (int i=0;i<2;i++)
    #pragma unroll
    for (int j=0;j<8;j++)
      #pragma unroll
      for (int k=0;k<4;k++) acc[i][j][k] = 0.f;

  auto LOAD = [&](int kt, int buf){
    #pragma unroll
    for (int u=0; u<4; u++){
      int id = tid + u*256;              // 0..1023 (A: 0..511, B: 512..1023)
      int half = id >> 9;
      int id2 = id & 511;
      int r = id2 >> 2, ch = id2 & 3;    // 128 rows x 4 chunks of 16B
      unsigned soff = (unsigned)(r*64 + ((ch ^ (r & 3)) << 4));
      const __nv_bfloat16* gp = (half ? Bg : Ag) + (size_t)r*Ksp + kt*32 + ch*8;
      unsigned sb = (half ? sB : sA) + buf*8192 + soff;
      CP16(sb, gp);
    }
  };

  LOAD(0,0); CP_COMMIT();
  for (int kt=0; kt<96; kt++){
    int buf = kt & 1;
    if (kt < 95){ LOAD(kt+1, buf^1); CP_COMMIT(); CP_WAIT1(); }
    else        { CP_WAIT0(); }
    __syncthreads();
    #pragma unroll
    for (int kk=0; kk<2; kk++){
      unsigned a[2][4];
      #pragma unroll
      for (int sm=0; sm<2; sm++){
        int r = wm*32 + sm*16 + (lane & 15);
        int c = kk*16 + (lane >> 4)*8;
        unsigned addr = sA + buf*8192 + (unsigned)(r*64 + (((c>>3) ^ (r&3)) << 4));
        ldsm_x4(addr, a[sm][0], a[sm][1], a[sm][2], a[sm][3]);
      }
      unsigned b[4][4];
      #pragma unroll
      for (int sn=0; sn<4; sn++){
        int r = wn*64 + sn*16 + (lane & 15);
        int c = kk*16 + (lane >> 4)*8;
        unsigned addr = sB + buf*8192 + (unsigned)(r*64 + (((c>>3) ^ (r&3)) << 4));
        ldsm_x4(addr, b[sn][0], b[sn][1], b[sn][2], b[sn][3]);
      }
      #pragma unroll
      for (int sm=0; sm<2; sm++)
        #pragma unroll
        for (int sn=0; sn<4; sn++){
          mma16816(acc[sm][2*sn+0][0], acc[sm][2*sn+0][1], acc[sm][2*sn+0][2], acc[sm][2*sn+0][3],
                   a[sm][0], a[sm][1], a[sm][2], a[sm][3], b[sn][0], b[sn][2]);
          mma16816(acc[sm][2*sn+1][0], acc[sm][2*sn+1][1], acc[sm][2*sn+1][2], acc[sm][2*sn+1][3],
                   a[sm][0], a[sm][1], a[sm][2], a[sm][3], b[sn][1], b[sn][3]);
        }
    }
    __syncthreads();
  }

  // epilogue: add combined bias, write fp32 projections
  #pragma unroll
  for (int sm=0; sm<2; sm++){
    #pragma unroll
    for (int nt=0; nt<8; nt++){
      int n = n0 + wn*64 + nt*8 + (lane & 3)*2;
      int gate = n >> 10, col = n & 1023;
      float b0v = g_biasi[n], b1v = g_biasi[n+1];
      #pragma unroll
      for (int hf=0; hf<2; hf++){
        int m = m0 + wm*32 + sm*16 + (lane >> 2) + hf*8;
        size_t off = (size_t)gate*PLANE + (size_t)m*Hn + col;
        float2 v; v.x = acc[sm][nt][hf*2+0] + b0v; v.y = acc[sm][nt][hf*2+1] + b1v;
        *reinterpret_cast<float2*>(&g_xproj[off]) = v;
      }
    }
  }
}

// ------------------------- persistent recurrence kernel -------------------------
// 64 CTAs x 256 threads, co-resident. Per step:
//   Phase A: pre = h2 @ Wzr^T  (this CTA: 32 of 2048 cols); z=sigmoid, r=sigmoid, rh=r*h
//   Phase B: pre = rh2 @ Wc2^T (this CTA: 16 of 1024 cols); cand=tanh; h update + output
__global__ void __launch_bounds__(256,1) k_recur(float* __restrict__ out){
  __shared__ __align__(128) __nv_bfloat16 As[2][64*64];   // 16 KB
  __shared__ __align__(128) __nv_bfloat16 Bsh[2][32*64];  //  8 KB (phase B uses first 2KB/buf)
  const int tid = threadIdx.x, lane = tid & 31, wid = tid >> 5;
  const int cta = blockIdx.x;
  const unsigned sA = (unsigned)__cvta_generic_to_shared(&As[0][0]);
  const unsigned sB = (unsigned)__cvta_generic_to_shared(&Bsh[0][0]);
  const unsigned ep0 = *(volatile unsigned*)&g_epoch;
  unsigned nb = 0;

  for (int t=0; t<Tn; t++){
    // =============== Phase A ===============
    {
      const int wm = wid & 3, wn = wid >> 2;   // warp tile 16m x 16n
      float acc[2][4];
      #pragma unroll
      for (int i=0;i<2;i++){ acc[i][0]=acc[i][1]=acc[i][2]=acc[i][3]=0.f; }
      const __nv_bfloat16* Bg = g_Wzr + (size_t)(cta*32) * Ksp;

      auto LOADA = [&](int kt, int buf){
        #pragma unroll
        for (int u=0; u<3; u++){
          int id = tid + u*256;                 // 0..767
          if (id < 512){                        // A: 64 rows x 8 chunks
            int r = id >> 3, ch = id & 7;
            CP16(sA + buf*8192 + (unsigned)(r*128 + ((ch ^ (r&7)) << 4)),
                 g_h2 + (size_t)r*Ksp + kt*64 + ch*8);
          } else {                              // B: 32 rows x 8 chunks
            int id2 = id - 512; int r = id2 >> 3, ch = id2 & 7;
            CP16(sB + buf*4096 + (unsigned)(r*128 + ((ch ^ (r&7)) << 4)),
                 Bg + (size_t)r*Ksp + kt*64 + ch*8);
          }
        }
      };

      LOADA(0,0); CP_COMMIT();
      for (int kt=0; kt<48; kt++){
        int buf = kt & 1;
        if (kt < 47){ LOADA(kt+1, buf^1); CP_COMMIT(); CP_WAIT1(); }
        else        { CP_WAIT0(); }
        __syncthreads();
        #pragma unroll
        for (int kk=0; kk<4; kk++){
          unsigned a0,a1,a2,a3;
          { int r = wm*16 + (lane & 15); int c = kk*16 + (lane >> 4)*8;
            ldsm_x4(sA + buf*8192 + (unsigned)(r*128 + (((c>>3) ^ (r&7)) << 4)), a0,a1,a2,a3); }
          unsigned b0,b1,b2,b3;
          { int r = wn*16 + (lane & 15); int c = kk*16 + (lane >> 4)*8;
            ldsm_x4(sB + buf*4096 + (unsigned)(r*128 + (((c>>3) ^ (r&7)) << 4)), b0,b1,b2,b3); }
          mma16816(acc[0][0],acc[0][1],acc[0][2],acc[0][3], a0,a1,a2,a3, b0,b2);
          mma16816(acc[1][0],acc[1][1],acc[1][2],acc[1][3], a0,a1,a2,a3, b1,b3);
        }
        __syncthreads();
      }

      // epilogue A
      #pragma unroll
      for (int nt=0; nt<2; nt++){
        int n = cta*32 + wn*16 + nt*8 + (lane & 3)*2;
        #pragma unroll
        for (int hf=0; hf<2; hf++){
          int b = wm*16 + (lane >> 2) + hf*8;
          float v0 = acc[nt][hf*2+0], v1 = acc[nt][hf*2+1];
          if (n < Hn){
            size_t xo = (size_t)(t*Bn + b)*Hn + n;
            g_z[b*Hn + n]     = sigm(g_xproj[xo]   + v0);
            g_z[b*Hn + n + 1] = sigm(g_xproj[xo+1] + v1);
          } else {
            int nc = n - Hn;
            size_t xo = PLANE + (size_t)(t*Bn + b)*Hn + nc;
            float r0 = sigm(g_xproj[xo]   + v0);
            float r1 = sigm(g_xproj[xo+1] + v1);
            float h0 = __ldcg(&g_h[b*Hn + nc]);
            float h1 = __ldcg(&g_h[b*Hn + nc + 1]);
            float rh0 = r0*h0, rh1 = r1*h1;
            __nv_bfloat16* p = g_rh2 + (size_t)b*Ksp;
            __nv_bfloat16 hi, lo;
            bsplit(rh0, hi, lo); p[nc]     = hi; p[Hn + nc]     = lo; p[2*Hn + nc]     = hi;
            bsplit(rh1, hi, lo); p[nc + 1] = hi; p[Hn + nc + 1] = lo; p[2*Hn + nc + 1] = hi;
          }
        }
      }
    }
    gridbar(ep0 + (++nb));

    // =============== Phase B ===============
    {
      const int wm = wid & 3, wn = (wid >> 2) & 1;  // warp tile 16m x 8n
      float acc[4] = {0.f, 0.f, 0.f, 0.f};
      const __nv_bfloat16* Bg = g_Wc2 + (size_t)(cta*16) * Ksp;

      auto LOADB = [&](int kt, int buf){
        #pragma unroll
        for (int u=0; u<3; u++){
          int id = tid + u*256;                 // 0..767 (need 0..639)
          if (id < 512){                        // A: g_rh2, 64 rows x 8 chunks
            int r = id >> 3, ch = id & 7;
            CP16(sA + buf*8192 + (unsigned)(r*128 + ((ch ^ (r&7)) << 4)),
                 g_rh2 + (size_t)r*Ksp + kt*64 + ch*8);
          } else if (id < 640){                 // B: 16 rows x 8 chunks
            int id2 = id - 512; int r = id2 >> 3, ch = id2 & 7;
            CP16(sB + buf*2048 + (unsigned)(r*128 + ((ch ^ (r&7)) << 4)),
                 Bg + (size_t)r*Ksp + kt*64 + ch*8);
          }
        }
      };

      LOADB(0,0); CP_COMMIT();
      for (int kt=0; kt<48; kt++){
        int buf = kt & 1;
        if (kt < 47){ LOADB(kt+1, buf^1); CP_COMMIT(); CP_WAIT1(); }
        else        { CP_WAIT0(); }
        __syncthreads();
        #pragma unroll
        for (int kk=0; kk<4; kk++){
          unsigned a0,a1,a2,a3;
          { int r = wm*16 + (lane & 15); int c = kk*16 + (lane >> 4)*8;
            ldsm_x4(sA + buf*8192 + (unsigned)(r*128 + (((c>>3) ^ (r&7)) << 4)), a0,a1,a2,a3); }
          unsigned b0,b1;
          { int l = lane & 15; int r = wn*8 + (l & 7); int c = kk*16 + (l >> 3)*8;
            ldsm_x2(sB + buf*2048 + (unsigned)(r*128 + (((c>>3) ^ (r&7)) << 4)), b0,b1); }
          mma16816(acc[0],acc[1],acc[2],acc[3], a0,a1,a2,a3, b0,b1);
        }
        __syncthreads();
      }

      // epilogue B: candidate, gate combine, h update, output
      int n = cta*16 + wn*8 + (lane & 3)*2;
      #pragma unroll
      for (int hf=0; hf<2; hf++){
        int b = wm*16 + (lane >> 2) + hf*8;
        float v0 = acc[hf*2+0], v1 = acc[hf*2+1];
        size_t xo = 2*PLANE + (size_t)(t*Bn + b)*Hn + n;
        float c0 = tanhf(g_xproj[xo]   + v0);
        float c1 = tanhf(g_xproj[xo+1] + v1);
        float z0 = __ldcg(&g_z[b*Hn + n]);
        float z1 = __ldcg(&g_z[b*Hn + n + 1]);
        float h0 = __ldcg(&g_h[b*Hn + n]);
        float h1 = __ldcg(&g_h[b*Hn + n + 1]);
        float hn0 = h0 + z0*(c0 - h0);
        float hn1 = h1 + z1*(c1 - h1);
        size_t oo = (size_t)(t*Bn + b)*Hn + n;
        out[oo]     = hn0;
        out[oo + 1] = hn1;
        g_h[b*Hn + n]     = hn0;
        g_h[b*Hn + n + 1] = hn1;
        __nv_bfloat16* p = g_h2 + (size_t)b*Ksp;
        __nv_bfloat16 hi, lo;
        bsplit(hn0, hi, lo); p[n]     = hi; p[Hn + n]     = lo; p[2*Hn + n]     = hi;
        bsplit(hn1, hi, lo); p[n + 1] = hi; p[Hn + n + 1] = lo; p[2*Hn + n + 1] = hi;
        if (t == Tn-1){
          size_t to = (size_t)Tn*Bn*Hn + (size_t)b*Hn + n;
          out[to]     = hn0;
          out[to + 1] = hn1;
        }
      }
    }
    gridbar(ep0 + (++nb));
  }
}

// ------------------------- launch -------------------------
extern "C" void kernel_launch(void* const* d_in, const int* in_sizes, int n_in,
                              void* d_out, int out_size){
  (void)in_sizes; (void)n_in; (void)out_size;
  const float* x   = (const float*)d_in[0];
  const float* hid = (const float*)d_in[1];
  const float* Wzi = (const float*)d_in[2];
  const float* bzi = (const float*)d_in[3];
  const float* Wzh = (const float*)d_in[4];
  const float* bzh = (const float*)d_in[5];
  const float* Wri = (const float*)d_in[6];
  const float* bri = (const float*)d_in[7];
  const float* Wrh = (const float*)d_in[8];
  const float* brh = (const float*)d_in[9];
  const float* Wci = (const float*)d_in[10];
  const float* bci = (const float*)d_in[11];
  const float* Wch = (const float*)d_in[12];
  const float* bch = (const float*)d_in[13];
  float* out = (float*)d_out;

  k_split_x<<<2048, 256>>>(x);
  k_prep_w<<<512, 256>>>(Wzi,bzi,Wzh,bzh,Wri,bri,Wrh,brh,Wci,bci,Wch,bch);
  k_init_h<<<64, 256>>>(hid);
  k_gemm_x<<<dim3(24, 256), 256>>>();
  k_recur<<<64, 256>>>(out);
}

// round 11
// speedup vs baseline: 1.2046x; 1.2046x over previous
#include <cuda_runtime.h>
#include <cuda_bf16.h>
#include <cstdint>
#include <cstddef>

#define Tn 512
#define Bn 64
#define In 1024
#define Hn 1024
#define MAll (Tn*Bn)          // 32768
#define Ksp 3072              // 3-term split K: [hi | lo | hi] (A)  /  [hi | hi | lo] (B)
#define N3 3072               // 3 gates * H
#define PLANE ((size_t)MAll*(size_t)Hn)

// ------------------------- scratch (static device allocations) -------------------------
__device__ __align__(256) __nv_bfloat16 g_x2[(size_t)MAll*Ksp];     // x split      (192 MB)
__device__ __align__(256) __nv_bfloat16 g_Wi2[(size_t)N3*Ksp];      // Wzi|Wri|Wci  ( 18 MB)
__device__ __align__(256) __nv_bfloat16 g_Wzr[(size_t)2048*Ksp];    // Wzh|Wrh      ( 12 MB)
__device__ __align__(256) __nv_bfloat16 g_Wc2[(size_t)1024*Ksp];    // Wch          (  6 MB)
__device__ __align__(256) float g_biasi[N3];                        // b?i + b?h
__device__ __align__(256) float g_xproj[(size_t)3*MAll*Hn];         // x proj + bias (402 MB)
__device__ __align__(256) float g_h[Bn*Hn];
__device__ __align__(256) __nv_bfloat16 g_h2[(size_t)Bn*Ksp];
__device__ __align__(256) float g_z[Bn*Hn];
__device__ __align__(256) __nv_bfloat16 g_rh2[(size_t)Bn*Ksp];
__device__ unsigned g_cnt;     // zero-initialized
__device__ unsigned g_epoch;   // monotonic across graph replays

// ------------------------- helpers -------------------------
__device__ __forceinline__ float sigm(float x){ return 1.0f/(1.0f + __expf(-x)); }

__device__ __forceinline__ void bsplit(float v, __nv_bfloat16 &hi, __nv_bfloat16 &lo){
  hi = __float2bfloat16(v);
  lo = __float2bfloat16(v - __bfloat162float(hi));
}

__device__ __forceinline__ void ldsm_x4(unsigned addr, unsigned &r0, unsigned &r1,
                                        unsigned &r2, unsigned &r3){
  asm volatile("ldmatrix.sync.aligned.m8n8.x4.shared.b16 {%0,%1,%2,%3}, [%4];\n"
    : "=r"(r0),"=r"(r1),"=r"(r2),"=r"(r3) : "r"(addr));
}
__device__ __forceinline__ void ldsm_x2(unsigned addr, unsigned &r0, unsigned &r1){
  asm volatile("ldmatrix.sync.aligned.m8n8.x2.shared.b16 {%0,%1}, [%2];\n"
    : "=r"(r0),"=r"(r1) : "r"(addr));
}
__device__ __forceinline__ void mma16816(float &c0,float &c1,float &c2,float &c3,
                                         unsigned a0,unsigned a1,unsigned a2,unsigned a3,
                                         unsigned b0,unsigned b1){
  asm volatile("mma.sync.aligned.m16n8k16.row.col.f32.bf16.bf16.f32 "
               "{%0,%1,%2,%3},{%4,%5,%6,%7},{%8,%9},{%0,%1,%2,%3};\n"
    : "+f"(c0),"+f"(c1),"+f"(c2),"+f"(c3)
    : "r"(a0),"r"(a1),"r"(a2),"r"(a3),"r"(b0),"r"(b1));
}
#define CP16(smem_u32, gptr) \
  asm volatile("cp.async.cg.shared.global [%0], [%1], 16;\n" :: "r"(smem_u32), "l"(gptr))
#define CP_COMMIT() asm volatile("cp.async.commit_group;\n")
#define CP_WAIT1()  asm volatile("cp.async.wait_group 1;\n")
#define CP_WAIT2()  asm volatile("cp.async.wait_group 2;\n")
#define CP_WAIT0()  asm volatile("cp.async.wait_group 0;\n")

// Grid barrier: epoch-monotonic (graph-replay safe), base epoch read per launch.
__device__ __forceinline__ void gridbar(unsigned target){
  __threadfence();
  __syncthreads();
  if (threadIdx.x == 0){
    unsigned old = atomicAdd(&g_cnt, 1);
    if (old == gridDim.x - 1){
      atomicExch(&g_cnt, 0);
      __threadfence();
      atomicAdd(&g_epoch, 1);
    } else {
      while (*(volatile unsigned*)&g_epoch < target) { __nanosleep(32); }
    }
  }
  __syncthreads();
}

// ------------------------- prep kernels -------------------------
__global__ void k_split_x(const float* __restrict__ x){
  size_t stride = (size_t)gridDim.x * blockDim.x;
  for (size_t i = (size_t)blockIdx.x*blockDim.x + threadIdx.x; i < (size_t)MAll*In; i += stride){
    size_t row = i >> 10; int col = (int)(i & 1023);
    __nv_bfloat16 hi, lo; bsplit(x[i], hi, lo);
    __nv_bfloat16* p = g_x2 + row*Ksp;
    p[col]        = hi;   // A-side: [hi | lo | hi]
    p[In + col]   = lo;
    p[2*In + col] = hi;
  }
}

// B-side split layout: [hi | hi | lo]
__device__ __forceinline__ void wsplit(float v, __nv_bfloat16* base, int c){
  __nv_bfloat16 hi, lo; bsplit(v, hi, lo);
  base[c]        = hi;
  base[In + c]   = hi;
  base[2*In + c] = lo;
}

__global__ void k_prep_w(const float* __restrict__ Wzi, const float* __restrict__ bzi,
                         const float* __restrict__ Wzh, const float* __restrict__ bzh,
                         const float* __restrict__ Wri, const float* __restrict__ bri,
                         const float* __restrict__ Wrh, const float* __restrict__ brh,
                         const float* __restrict__ Wci, const float* __restrict__ bci,
                         const float* __restrict__ Wch, const float* __restrict__ bch){
  int stride = gridDim.x * blockDim.x;
  for (int i = blockIdx.x*blockDim.x + threadIdx.x; i < Hn*In; i += stride){
    int r = i >> 10, c = i & 1023;
    wsplit(Wzi[i], g_Wi2 + (size_t)r*Ksp,        c);
    wsplit(Wri[i], g_Wi2 + (size_t)(Hn+r)*Ksp,   c);
    wsplit(Wci[i], g_Wi2 + (size_t)(2*Hn+r)*Ksp, c);
    wsplit(Wzh[i], g_Wzr + (size_t)r*Ksp,        c);
    wsplit(Wrh[i], g_Wzr + (size_t)(Hn+r)*Ksp,   c);
    wsplit(Wch[i], g_Wc2 + (size_t)r*Ksp,        c);
  }
  for (int n = blockIdx.x*blockDim.x + threadIdx.x; n < N3; n += stride){
    float b = (n < Hn)   ? (bzi[n] + bzh[n])
            : (n < 2*Hn) ? (bri[n-Hn] + brh[n-Hn])
                         : (bci[n-2*Hn] + bch[n-2*Hn]);
    g_biasi[n] = b;
  }
}

__global__ void k_init_h(const float* __restrict__ hidden){
  int stride = gridDim.x * blockDim.x;
  for (int i = blockIdx.x*blockDim.x + threadIdx.x; i < Bn*Hn; i += stride){
    int b = i >> 10, c = i & 1023;
    float v = hidden[i];
    g_h[i] = v;
    __nv_bfloat16 hi, lo; bsplit(v, hi, lo);
    __nv_bfloat16* p = g_h2 + (size_t)b*Ksp;
    p[c]        = hi;
    p[In + c]   = lo;
    p[2*In + c] = hi;
  }
}

// ------------------------- input projection GEMM -------------------------
// C[m, n] = sum_k x2[m,k] * Wi2[n,k] + bias[n]  ->  g_xproj[gate][m][n%1024]
// M=32768, N=3072, K=3072. BM=128, BN=128, BK=32, 256 threads (8 warps 4x2).
// 3-stage cp.async pipeline, one __syncthreads per chunk.
__global__ void __launch_bounds__(256,1) k_gemm_x(){
  __shared__ __align__(128) __nv_bfloat16 As[3][128*32];   // 24 KB
  __shared__ __align__(128) __nv_bfloat16 Bs[3][128*32];   // 24 KB
  const int tid = threadIdx.x, lane = tid & 31, wid = tid >> 5;
  const int wm = wid & 3, wn = wid >> 2;                 // warp tile 32m x 64n
  const int m0 = blockIdx.y * 128, n0 = blockIdx.x * 128;
  const unsigned sA = (unsigned)__cvta_generic_to_shared(&As[0][0]);
  const unsigned sB = (unsigned)__cvta_generic_to_shared(&Bs[0][0]);
  const __nv_bfloat16* Ag = g_x2 + (size_t)m0 * Ksp;
  const __nv_bfloat16* Bg = g_Wi2 + (size_t)n0 * Ksp;
  const int KT = 96;

  float acc[2][8][4];
  #pragma unroll
  for (int i=0;i<2;i++)
    #pragma unroll
    for (int j=0;j<8;j++)
      #pragma unroll
      for (int k=0;k<4;k++) acc[i][j][k] = 0.f;

  auto LOAD = [&](int kt, int buf){
    #pragma unroll
    for (int u=0; u<4; u++){
      int id = tid + u*256;              // 0..1023 (A: 0..511, B: 512..1023)
      int half = id >> 9;
      int id2 = id & 511;
      int r = id2 >> 2, ch = id2 & 3;    // 128 rows x 4 chunks of 16B
      unsigned soff = (unsigned)(r*64 + ((ch ^ (r & 3)) << 4));
      const __nv_bfloat16* gp = (half ? Bg : Ag) + (size_t)r*Ksp + kt*32 + ch*8;
      unsigned sb = (half ? sB : sA) + buf*8192 + soff;
      CP16(sb, gp);
    }
  };

  LOAD(0,0); CP_COMMIT();
  LOAD(1,1); CP_COMMIT();
  for (int kt=0; kt<KT; kt++){
    CP_WAIT1();                          // stage kt complete
    __syncthreads();                     // all warps done with buf being overwritten
    int nk = kt + 2;
    if (nk < KT) LOAD(nk, nk % 3);
    CP_COMMIT();                         // uniform commit (empty group at tail)
    int buf = kt % 3;
    #pragma unroll
    for (int kk=0; kk<2; kk++){
      unsigned a[2][4];
      #pragma unroll
      for (int sm=0; sm<2; sm++){
        int r = wm*32 + sm*16 + (lane & 15);
        int c = kk*16 + (lane >> 4)*8;
        unsigned addr = sA + buf*8192 + (unsigned)(r*64 + (((c>>3) ^ (r&3)) << 4));
        ldsm_x4(addr, a[sm][0], a[sm][1], a[sm][2], a[sm][3]);
      }
      unsigned b[4][4];
      #pragma unroll
      for (int sn=0; sn<4; sn++){
        int r = wn*64 + sn*16 + (lane & 15);
        int c = kk*16 + (lane >> 4)*8;
        unsigned addr = sB + buf*8192 + (unsigned)(r*64 + (((c>>3) ^ (r&3)) << 4));
        ldsm_x4(addr, b[sn][0], b[sn][1], b[sn][2], b[sn][3]);
      }
      #pragma unroll
      for (int sm=0; sm<2; sm++)
        #pragma unroll
        for (int sn=0; sn<4; sn++){
          mma16816(acc[sm][2*sn+0][0], acc[sm][2*sn+0][1], acc[sm][2*sn+0][2], acc[sm][2*sn+0][3],
                   a[sm][0], a[sm][1], a[sm][2], a[sm][3], b[sn][0], b[sn][2]);
          mma16816(acc[sm][2*sn+1][0], acc[sm][2*sn+1][1], acc[sm][2*sn+1][2], acc[sm][2*sn+1][3],
                   a[sm][0], a[sm][1], a[sm][2], a[sm][3], b[sn][1], b[sn][3]);
        }
    }
  }

  // epilogue: add combined bias, write fp32 projections
  #pragma unroll
  for (int sm=0; sm<2; sm++){
    #pragma unroll
    for (int nt=0; nt<8; nt++){
      int n = n0 + wn*64 + nt*8 + (lane & 3)*2;
      int gate = n >> 10, col = n & 1023;
      float b0v = g_biasi[n], b1v = g_biasi[n+1];
      #pragma unroll
      for (int hf=0; hf<2; hf++){
        int m = m0 + wm*32 + sm*16 + (lane >> 2) + hf*8;
        size_t off = (size_t)gate*PLANE + (size_t)m*Hn + col;
        float2 v; v.x = acc[sm][nt][hf*2+0] + b0v; v.y = acc[sm][nt][hf*2+1] + b1v;
        *reinterpret_cast<float2*>(&g_xproj[off]) = v;
      }
    }
  }
}

// ------------------------- persistent recurrence kernel -------------------------
// 64 CTAs x 256 threads, co-resident. 4-stage cp.async pipeline per phase.
// Epilogue operands (xproj / h / z) are register-prefetched at phase start so their
// DRAM/L2 latency hides under the GEMM mainloop.
//   Phase A: pre = h2 @ Wzr^T  (this CTA: 32 of 2048 cols); z=sigmoid, r=sigmoid, rh=r*h
//   Phase B: pre = rh2 @ Wc2^T (this CTA: 16 of 1024 cols); cand=tanh; h update + output
__global__ void __launch_bounds__(256,1) k_recur(float* __restrict__ out){
  __shared__ __align__(128) __nv_bfloat16 As[4][64*64];   // 32 KB
  __shared__ __align__(128) __nv_bfloat16 Bsh[4][32*64];  // 16 KB
  const int tid = threadIdx.x, lane = tid & 31, wid = tid >> 5;
  const int cta = blockIdx.x;
  const unsigned sA = (unsigned)__cvta_generic_to_shared(&As[0][0]);
  const unsigned sB = (unsigned)__cvta_generic_to_shared(&Bsh[0][0]);
  const unsigned ep0 = *(volatile unsigned*)&g_epoch;
  unsigned nb = 0;
  const int KT = 48;

  for (int t=0; t<Tn; t++){
    // =============== Phase A ===============
    {
      const int wm = wid & 3, wn = wid >> 2;   // warp tile 16m x 16n
      float acc[2][4];
      #pragma unroll
      for (int i=0;i<2;i++){ acc[i][0]=acc[i][1]=acc[i][2]=acc[i][3]=0.f; }
      const __nv_bfloat16* Bg = g_Wzr + (size_t)(cta*32) * Ksp;

      // ---- epilogue-operand prefetch (safe: after gridbar of previous step) ----
      // n range for this CTA never straddles 1024, so the z/r branch is CTA-uniform.
      float2 xpA[2][2]; float2 hA[2][2];
      #pragma unroll
      for (int nt=0; nt<2; nt++){
        int n = cta*32 + wn*16 + nt*8 + (lane & 3)*2;
        #pragma unroll
        for (int hf=0; hf<2; hf++){
          int b = wm*16 + (lane >> 2) + hf*8;
          size_t xo = (size_t)(n >> 10)*PLANE + (size_t)(t*Bn + b)*Hn + (n & 1023);
          xpA[nt][hf] = __ldcs(reinterpret_cast<const float2*>(&g_xproj[xo]));
          if (n >= Hn){
            int nc = n - Hn;
            hA[nt][hf].x = __ldcg(&g_h[b*Hn + nc]);
            hA[nt][hf].y = __ldcg(&g_h[b*Hn + nc + 1]);
          }
        }
      }

      auto LOADA = [&](int kt, int buf){
        #pragma unroll
        for (int u=0; u<3; u++){
          int id = tid + u*256;                 // 0..767
          if (id < 512){                        // A: 64 rows x 8 chunks
            int r = id >> 3, ch = id & 7;
            CP16(sA + buf*8192 + (unsigned)(r*128 + ((ch ^ (r&7)) << 4)),
                 g_h2 + (size_t)r*Ksp + kt*64 + ch*8);
          } else {                              // B: 32 rows x 8 chunks
            int id2 = id - 512; int r = id2 >> 3, ch = id2 & 7;
            CP16(sB + buf*4096 + (unsigned)(r*128 + ((ch ^ (r&7)) << 4)),
                 Bg + (size_t)r*Ksp + kt*64 + ch*8);
          }
        }
      };

      LOADA(0,0); CP_COMMIT();
      LOADA(1,1); CP_COMMIT();
      LOADA(2,2); CP_COMMIT();
      for (int kt=0; kt<KT; kt++){
        CP_WAIT2();                        // stage kt complete
        __syncthreads();
        int nk = kt + 3;
        if (nk < KT) LOADA(nk, nk & 3);
        CP_COMMIT();
        int buf = kt & 3;
        #pragma unroll
        for (int kk=0; kk<4; kk++){
          unsigned a0,a1,a2,a3;
          { int r = wm*16 + (lane & 15); int c = kk*16 + (lane >> 4)*8;
            ldsm_x4(sA + buf*8192 + (unsigned)(r*128 + (((c>>3) ^ (r&7)) << 4)), a0,a1,a2,a3); }
          unsigned b0,b1,b2,b3;
          { int r = wn*16 + (lane & 15); int c = kk*16 + (lane >> 4)*8;
            ldsm_x4(sB + buf*4096 + (unsigned)(r*128 + (((c>>3) ^ (r&7)) << 4)), b0,b1,b2,b3); }
          mma16816(acc[0][0],acc[0][1],acc[0][2],acc[0][3], a0,a1,a2,a3, b0,b2);
          mma16816(acc[1][0],acc[1][1],acc[1][2],acc[1][3], a0,a1,a2,a3, b1,b3);
        }
      }

      // epilogue A (uses prefetched operands)
      #pragma unroll
      for (int nt=0; nt<2; nt++){
        int n = cta*32 + wn*16 + nt*8 + (lane & 3)*2;
        #pragma unroll
        for (int hf=0; hf<2; hf++){
          int b = wm*16 + (lane >> 2) + hf*8;
          float v0 = acc[nt][hf*2+0], v1 = acc[nt][hf*2+1];
          if (n < Hn){
            g_z[b*Hn + n]     = sigm(xpA[nt][hf].x + v0);
            g_z[b*Hn + n + 1] = sigm(xpA[nt][hf].y + v1);
          } else {
            int nc = n - Hn;
            float r0 = sigm(xpA[nt][hf].x + v0);
            float r1 = sigm(xpA[nt][hf].y + v1);
            float rh0 = r0*hA[nt][hf].x, rh1 = r1*hA[nt][hf].y;
            __nv_bfloat16* p = g_rh2 + (size_t)b*Ksp;
            __nv_bfloat16 hi, lo;
            bsplit(rh0, hi, lo); p[nc]     = hi; p[Hn + nc]     = lo; p[2*Hn + nc]     = hi;
            bsplit(rh1, hi, lo); p[nc + 1] = hi; p[Hn + nc + 1] = lo; p[2*Hn + nc + 1] = hi;
          }
        }
      }
    }
    gridbar(ep0 + (++nb));

    // =============== Phase B ===============
    {
      const int wm = wid & 3, wn = (wid >> 2) & 1;  // warp tile 16m x 8n
      float acc[4] = {0.f, 0.f, 0.f, 0.f};
      const __nv_bfloat16* Bg = g_Wc2 + (size_t)(cta*16) * Ksp;

      // ---- epilogue-operand prefetch (safe: after gridbar above) ----
      const int nB = cta*16 + wn*8 + (lane & 3)*2;
      float2 xpB[2], zB[2], hB[2];
      #pragma unroll
      for (int hf=0; hf<2; hf++){
        int b = wm*16 + (lane >> 2) + hf*8;
        size_t xo = 2*PLANE + (size_t)(t*Bn + b)*Hn + nB;
        xpB[hf] = __ldcs(reinterpret_cast<const float2*>(&g_xproj[xo]));
        zB[hf].x = __ldcg(&g_z[b*Hn + nB]);
        zB[hf].y = __ldcg(&g_z[b*Hn + nB + 1]);
        hB[hf].x = __ldcg(&g_h[b*Hn + nB]);
        hB[hf].y = __ldcg(&g_h[b*Hn + nB + 1]);
      }

      auto LOADB = [&](int kt, int buf){
        #pragma unroll
        for (int u=0; u<3; u++){
          int id = tid + u*256;                 // 0..767 (need 0..639)
          if (id < 512){                        // A: g_rh2, 64 rows x 8 chunks
            int r = id >> 3, ch = id & 7;
            CP16(sA + buf*8192 + (unsigned)(r*128 + ((ch ^ (r&7)) << 4)),
                 g_rh2 + (size_t)r*Ksp + kt*64 + ch*8);
          } else if (id < 640){                 // B: 16 rows x 8 chunks
            int id2 = id - 512; int r = id2 >> 3, ch = id2 & 7;
            CP16(sB + buf*4096 + (unsigned)(r*128 + ((ch ^ (r&7)) << 4)),
                 Bg + (size_t)r*Ksp + kt*64 + ch*8);
          }
        }
      };

      LOADB(0,0); CP_COMMIT();
      LOADB(1,1); CP_COMMIT();
      LOADB(2,2); CP_COMMIT();
      for (int kt=0; kt<KT; kt++){
        CP_WAIT2();
        __syncthreads();
        int nk = kt + 3;
        if (nk < KT) LOADB(nk, nk & 3);
        CP_COMMIT();
        int buf = kt & 3;
        #pragma unroll
        for (int kk=0; kk<4; kk++){
          unsigned a0,a1,a2,a3;
          { int r = wm*16 + (lane & 15); int c = kk*16 + (lane >> 4)*8;
            ldsm_x4(sA + buf*8192 + (unsigned)(r*128 + (((c>>3) ^ (r&7)) << 4)), a0,a1,a2,a3); }
          unsigned b0,b1;
          { int l = lane & 15; int r = wn*8 + (l & 7); int c = kk*16 + (l >> 3)*8;
            ldsm_x2(sB + buf*4096 + (unsigned)(r*128 + (((c>>3) ^ (r&7)) << 4)), b0,b1); }
          mma16816(acc[0],acc[1],acc[2],acc[3], a0,a1,a2,a3, b0,b1);
        }
      }

      // epilogue B: candidate, gate combine, h update, output (prefetched operands)
      #pragma unroll
      for (int hf=0; hf<2; hf++){
        int b = wm*16 + (lane >> 2) + hf*8;
        float v0 = acc[hf*2+0], v1 = acc[hf*2+1];
        float c0 = tanhf(xpB[hf].x + v0);
        float c1 = tanhf(xpB[hf].y + v1);
        float h0 = hB[hf].x, h1 = hB[hf].y;
        float hn0 = h0 + zB[hf].x*(c0 - h0);
        float hn1 = h1 + zB[hf].y*(c1 - h1);
        size_t oo = (size_t)(t*Bn + b)*Hn + nB;
        out[oo]     = hn0;
        out[oo + 1] = hn1;
        g_h[b*Hn + nB]     = hn0;
        g_h[b*Hn + nB + 1] = hn1;
        __nv_bfloat16* p = g_h2 + (size_t)b*Ksp;
        __nv_bfloat16 hi, lo;
        bsplit(hn0, hi, lo); p[nB]     = hi; p[Hn + nB]     = lo; p[2*Hn + nB]     = hi;
        bsplit(hn1, hi, lo); p[nB + 1] = hi; p[Hn + nB + 1] = lo; p[2*Hn + nB + 1] = hi;
        if (t == Tn-1){
          size_t to = (size_t)Tn*Bn*Hn + (size_t)b*Hn + nB;
          out[to]     = hn0;
          out[to + 1] = hn1;
        }
      }
    }
    gridbar(ep0 + (++nb));
  }
}

// ------------------------- launch -------------------------
extern "C" void kernel_launch(void* const* d_in, const int* in_sizes, int n_in,
                              void* d_out, int out_size){
  (void)in_sizes; (void)n_in; (void)out_size;
  const float* x   = (const float*)d_in[0];
  const float* hid = (const float*)d_in[1];
  const float* Wzi = (const float*)d_in[2];
  const float* bzi = (const float*)d_in[3];
  const float* Wzh = (const float*)d_in[4];
  const float* bzh = (const float*)d_in[5];
  const float* Wri = (const float*)d_in[6];
  const float* bri = (const float*)d_in[7];
  const float* Wrh = (const float*)d_in[8];
  const float* brh = (const float*)d_in[9];
  const float* Wci = (const float*)d_in[10];
  const float* bci = (const float*)d_in[11];
  const float* Wch = (const float*)d_in[12];
  const float* bch = (const float*)d_in[13];
  float* out = (float*)d_out;

  k_split_x<<<2048, 256>>>(x);
  k_prep_w<<<512, 256>>>(Wzi,bzi,Wzh,bzh,Wri,bri,Wrh,brh,Wci,bci,Wch,bch);
  k_init_h<<<64, 256>>>(hid);
  k_gemm_x<<<dim3(24, 256), 256>>>();
  k_recur<<<64, 256>>>(out);
}